// round 7
// baseline (speedup 1.0000x reference)
#include <cuda_runtime.h>
#include <cuda_bf16.h>

// Problem constants (fixed by the reference)
#define NN 4096
#define KK 32
#define DD 256
#define HH 128
#define GG 384   // 3*H
#define NR (NN + KK)   // h1 rows incl. one pad row per (possibly empty) cluster

typedef unsigned long long ull;

// ---------------- device scratch (no allocations allowed) ----------------
static __device__ float4 g_wih0p[64 * GG];   // W_ih0 packed [k4][g]
static __device__ float4 g_wih1p[32 * GG];   // W_ih1 packed [k4][g]
static __device__ float  g_xw0[NN * GG];     // x @ W_ih0^T + b_ih0
static __device__ float  g_xwz[GG];          // b_ih0 (zero-input row for empty clusters)
static __device__ float  g_h1[NR * HH];      // layer-0 hidden sequence
static __device__ float  g_xw1[NR * GG];     // h1 @ W_ih1^T + b_ih1
static __device__ int    g_sorted[NN];
static __device__ int    g_off[KK + 1];
static __device__ int    g_len[KK];
static __device__ float  g_emb[KK * HH];
static __device__ float  g_scores[NN];

// ---------------- helpers ----------------
static __device__ __forceinline__ ull ffma2(ull a, ull b, ull c) {
    ull d;
    asm("fma.rn.f32x2 %0, %1, %2, %3;" : "=l"(d) : "l"(a), "l"(b), "l"(c));
    return d;
}
static __device__ __forceinline__ float f2sum(ull v) {
    float a, b;
    asm("mov.b64 {%0, %1}, %2;" : "=f"(a), "=f"(b) : "l"(v));
    return a + b;
}
static __device__ __forceinline__ float ex2_(float x) {
    float y; asm("ex2.approx.f32 %0, %1;" : "=f"(y) : "f"(x)); return y;
}
static __device__ __forceinline__ float rcp_(float x) {
    float y; asm("rcp.approx.f32 %0, %1;" : "=f"(y) : "f"(x)); return y;
}
#define L2E 1.4426950408889634f
static __device__ __forceinline__ float fast_sigmoid(float x) {
    return rcp_(1.0f + ex2_(-x * L2E));
}
static __device__ __forceinline__ float fast_tanh(float x) {
    x = fminf(x, 20.0f);
    float e = ex2_(x * (2.0f * L2E));
    return (e - 1.0f) * rcp_(e + 1.0f);
}

// ---------------- kernel: cluster ordering (stable, parallel) ----------------
__global__ void k_setup(const int* __restrict__ labels) {
    __shared__ int ls[NN];
    __shared__ int cnt[8][KK];
    __shared__ int soff[8][KK];
    int t = threadIdx.x;                 // 256 threads
    for (int i = t; i < NN; i += 256) ls[i] = labels[i];
    __syncthreads();
    int w = t >> 5, k = t & 31;
    {
        int c = 0;
        const int4* p = (const int4*)(ls + w * 512);
        for (int ii = 0; ii < 128; ++ii) {
            int4 v = p[ii];
            c += (v.x == k) + (v.y == k) + (v.z == k) + (v.w == k);
        }
        cnt[w][k] = c;
    }
    __syncthreads();
    if (w == 0) {
        int tot = 0;
        #pragma unroll
        for (int s = 0; s < 8; ++s) tot += cnt[s][k];
        g_len[k] = tot;
        int v = tot;
        #pragma unroll
        for (int d = 1; d < 32; d <<= 1) {
            int y = __shfl_up_sync(0xffffffffu, v, d);
            if (k >= d) v += y;
        }
        int off = v - tot;
        g_off[k] = off;
        if (k == 31) g_off[32] = off + tot;
        int run = off;
        #pragma unroll
        for (int s = 0; s < 8; ++s) { soff[s][k] = run; run += cnt[s][k]; }
    }
    __syncthreads();
    {
        int c = soff[w][k];
        const int4* p = (const int4*)(ls + w * 512);
        for (int ii = 0; ii < 128; ++ii) {
            int4 v = p[ii];
            int b = w * 512 + ii * 4;
            if (v.x == k) g_sorted[c++] = b;
            if (v.y == k) g_sorted[c++] = b + 1;
            if (v.z == k) g_sorted[c++] = b + 2;
            if (v.w == k) g_sorted[c++] = b + 3;
        }
    }
}

// ---------------- kernel: pack input weights + zero-input row ----------------
__global__ void k_pack(const float* __restrict__ wih0, const float* __restrict__ wih1,
                       const float* __restrict__ b_ih0) {
    int b = blockIdx.x;          // 0..95
    int g = threadIdx.x;         // 0..383
    if (b < 64) {
        const float* row = wih0 + (size_t)g * DD + b * 4;
        g_wih0p[b * GG + g] = make_float4(row[0], row[1], row[2], row[3]);
        if (b == 0) g_xwz[g] = b_ih0[g];
    } else {
        int k4 = b - 64;
        const float* row = wih1 + (size_t)g * HH + k4 * 4;
        g_wih1p[k4 * GG + g] = make_float4(row[0], row[1], row[2], row[3]);
    }
}

// ---------------- kernel: xw0 = x @ W_ih0^T + b_ih0 ----------------
__global__ void __launch_bounds__(384) k_xw0(const float* __restrict__ x,
                                             const float* __restrict__ b_ih0) {
    __shared__ __align__(16) float xs[16 * DD];   // 16 KB
    int r0 = blockIdx.x * 16;
    {
        const float4* xsrc = reinterpret_cast<const float4*>(x + (size_t)r0 * DD);
        float4* xd = reinterpret_cast<float4*>(xs);
        for (int i = threadIdx.x; i < 16 * DD / 4; i += 384) xd[i] = xsrc[i];
    }
    __syncthreads();
    int g = threadIdx.x;
    ull acc[16];
    #pragma unroll
    for (int s = 0; s < 16; ++s) acc[s] = 0ull;
    const ulonglong2* W = reinterpret_cast<const ulonglong2*>(g_wih0p) + g;
    #pragma unroll 8
    for (int k4 = 0; k4 < 64; ++k4) {
        ulonglong2 w = W[k4 * GG];
        #pragma unroll
        for (int s = 0; s < 16; ++s) {
            ulonglong2 xv = *reinterpret_cast<const ulonglong2*>(&xs[s * DD + k4 * 4]);
            acc[s] = ffma2(w.x, xv.x, acc[s]);
            acc[s] = ffma2(w.y, xv.y, acc[s]);
        }
    }
    float bi = b_ih0[g];
    #pragma unroll
    for (int s = 0; s < 16; ++s)
        g_xw0[(size_t)(r0 + s) * GG + g] = f2sum(acc[s]) + bi;
}

// ---------------- kernel: xw1 = h1 @ W_ih1^T + b_ih1 (NR rows) ----------------
__global__ void __launch_bounds__(384) k_xw1(const float* __restrict__ b_ih1) {
    __shared__ __align__(16) float xs[16 * HH];   // 8 KB
    int r0 = blockIdx.x * 16;
    {
        const float4* xsrc = reinterpret_cast<const float4*>(g_h1 + (size_t)r0 * HH);
        float4* xd = reinterpret_cast<float4*>(xs);
        for (int i = threadIdx.x; i < 16 * HH / 4; i += 384) xd[i] = xsrc[i];
    }
    __syncthreads();
    int g = threadIdx.x;
    ull acc[16];
    #pragma unroll
    for (int s = 0; s < 16; ++s) acc[s] = 0ull;
    const ulonglong2* W = reinterpret_cast<const ulonglong2*>(g_wih1p) + g;
    #pragma unroll 8
    for (int k4 = 0; k4 < 32; ++k4) {
        ulonglong2 w = W[k4 * GG];
        #pragma unroll
        for (int s = 0; s < 16; ++s) {
            ulonglong2 xv = *reinterpret_cast<const ulonglong2*>(&xs[s * HH + k4 * 4]);
            acc[s] = ffma2(w.x, xv.x, acc[s]);
            acc[s] = ffma2(w.y, xv.y, acc[s]);
        }
    }
    float bi = b_ih1[g];
    #pragma unroll
    for (int s = 0; s < 16; ++s)
        g_xw1[(size_t)(r0 + s) * GG + g] = f2sum(acc[s]) + bi;
}

// ---------------- kernel: single-layer GRU recurrence, ONE CTA per cluster ----
// 768 threads: thread (rr = t>>1, kh = t&1) computes half of gate row rr's dot
// product (64 of 128 h-columns): 48 columns from 12 register-resident
// ulonglong2, 16 columns from smem (stride-34 float2 layout, conflict-free).
// Pair-combine via shfl_xor(1); hw write by kh==0. 24 warps/SM (6 per SMSP)
// halve per-warp chains and hide bar/gate latency. No cross-SM traffic.
// pass 0: input = g_xw0[g_sorted[...]] rows, writes h1 sequence to g_h1.
// pass 1: input = g_xw1 rows (sequential), writes final h to g_emb.
__global__ void __launch_bounds__(768, 1) k_gru(const float* __restrict__ W,
                                                const float* __restrict__ bh,
                                                int pass) {
    __shared__ __align__(16) float h[HH];
    __shared__ float hw[GG];
    __shared__ __align__(8) float wsm[GG * 34];   // [row]: 2x16 tail cols, stride 34

    const int t = threadIdx.x;          // 0..767
    const int c = blockIdx.x;
    const int rr = t >> 1;              // gate row 0..383
    const int kh = t & 1;               // column half

    // ---- weight load: regs = cols [64kh, 64kh+48), smem = cols [64kh+48, 64kh+64)
    ulonglong2 w[12];
    {
        const ulonglong2* wr =
            reinterpret_cast<const ulonglong2*>(W + (size_t)rr * HH + 64 * kh);
        #pragma unroll
        for (int i = 0; i < 12; ++i) w[i] = wr[i];
        #pragma unroll
        for (int qq = 0; qq < 4; ++qq) {
            float4 v = *reinterpret_cast<const float4*>(
                W + (size_t)rr * HH + 64 * kh + 48 + 4 * qq);
            *(float2*)&wsm[rr * 34 + kh * 16 + 4 * qq]     = make_float2(v.x, v.y);
            *(float2*)&wsm[rr * 34 + kh * 16 + 4 * qq + 2] = make_float2(v.z, v.w);
        }
    }
    float bias = bh[rr];
    if (t < HH) h[t] = 0.f;

    const int len = g_len[c], off = g_off[c];
    const int len_e = max(len, 1);

    // ---- input prefetch (threads 0..127 hold the 3 gate inputs for slot t)
    float xr = 0.f, xz = 0.f, xn = 0.f;
    int nidx = 0;
    if (t < HH) {
        const float* r0;
        if (pass == 0) r0 = (len > 0) ? (g_xw0 + (size_t)g_sorted[off] * GG) : g_xwz;
        else           r0 = g_xw1 + (size_t)((len > 0) ? off : (NN + c)) * GG;
        xr = r0[t]; xz = r0[HH + t]; xn = r0[2 * HH + t];
        if (pass == 0 && len > 1) nidx = g_sorted[off + 1];
    }
    __syncthreads();

    for (int it = 0; it < len_e; ++it) {
        // ---- half-row dot product: regs part (48 cols) + smem tail (16 cols)
        ull ax = 0ull, ay = 0ull, az = 0ull;
        const ulonglong2* hp = reinterpret_cast<const ulonglong2*>(h + 64 * kh);
        #pragma unroll
        for (int i = 0; i < 12; ++i) {
            ulonglong2 hv = hp[i];
            ax = ffma2(w[i].x, hv.x, ax);
            ay = ffma2(w[i].y, hv.y, ay);
        }
        #pragma unroll
        for (int j = 0; j < 8; ++j) {
            ull wv = *(const ull*)&wsm[rr * 34 + kh * 16 + 2 * j];
            ull hv = *(const ull*)&h[64 * kh + 48 + 2 * j];
            az = ffma2(wv, hv, az);
        }
        float s = f2sum(ax) + f2sum(ay) + f2sum(az);
        s += __shfl_xor_sync(0xffffffffu, s, 1);   // combine the two halves
        if (kh == 0) hw[rr] = s + bias;
        __syncthreads();

        // ---- gate update (threads 0..127)
        if (t < HH) {
            float r = fast_sigmoid(xr + hw[t]);
            float z = fast_sigmoid(xz + hw[HH + t]);
            float n = fast_tanh(xn + r * hw[2 * HH + t]);
            float hn = (1.0f - z) * n + z * h[t];
            h[t] = hn;
            if (pass == 0) {
                int orow = (len > 0) ? (off + it) : (NN + c);
                g_h1[(size_t)orow * HH + t] = hn;
            }
            // prefetch next step's input row
            if (it + 1 < len_e) {
                const float* rn;
                if (pass == 0) rn = g_xw0 + (size_t)nidx * GG;
                else           rn = g_xw1 + (size_t)(off + it + 1) * GG;
                xr = rn[t]; xz = rn[HH + t]; xn = rn[2 * HH + t];
                if (pass == 0 && it + 2 < len) nidx = g_sorted[off + it + 2];
            }
        }
        __syncthreads();
    }

    if (pass == 1 && t < HH) g_emb[c * HH + t] = h[t];
}

// ---------------- kernel: per-sentence tanh scores (weight-norm fused) -------
__global__ void __launch_bounds__(128) k_score(const float* __restrict__ x,
                                               const int* __restrict__ labels,
                                               const float* __restrict__ lin_v,
                                               const float* __restrict__ lin_g,
                                               const float* __restrict__ lin_b) {
    __shared__ __align__(16) float wns[GG];
    __shared__ __align__(16) float embs[KK][132];  // padded
    __shared__ float redw[4];
    int t = threadIdx.x;
    float v0 = lin_v[t], v1 = lin_v[HH + t], v2 = lin_v[2 * HH + t];
    float ss = v0 * v0 + v1 * v1 + v2 * v2;
    #pragma unroll
    for (int d = 16; d >= 1; d >>= 1) ss += __shfl_xor_sync(0xffffffffu, ss, d);
    if ((t & 31) == 0) redw[t >> 5] = ss;
    __syncthreads();
    float scale = lin_g[0] / sqrtf(redw[0] + redw[1] + redw[2] + redw[3]);
    wns[t] = v0 * scale; wns[HH + t] = v1 * scale; wns[2 * HH + t] = v2 * scale;
    for (int i = t; i < KK * HH; i += 128) embs[i >> 7][i & 127] = g_emb[i];
    __syncthreads();
    int i = blockIdx.x * 128 + t;
    int lab = labels[i];
    const float4* xr = reinterpret_cast<const float4*>(x) + (size_t)i * (DD / 4);
    float acc = 0.f;
    #pragma unroll 8
    for (int k4 = 0; k4 < DD / 4; ++k4) {
        float4 xv = xr[k4];
        float4 wv = *reinterpret_cast<const float4*>(&wns[k4 * 4]);
        acc = fmaf(xv.x, wv.x, acc); acc = fmaf(xv.y, wv.y, acc);
        acc = fmaf(xv.z, wv.z, acc); acc = fmaf(xv.w, wv.w, acc);
    }
    #pragma unroll 8
    for (int k4 = 0; k4 < HH / 4; ++k4) {
        float4 ev = *reinterpret_cast<const float4*>(&embs[lab][k4 * 4]);
        float4 wv = *reinterpret_cast<const float4*>(&wns[DD + k4 * 4]);
        acc = fmaf(ev.x, wv.x, acc); acc = fmaf(ev.y, wv.y, acc);
        acc = fmaf(ev.z, wv.z, acc); acc = fmaf(ev.w, wv.w, acc);
    }
    g_scores[i] = tanhf(acc + lin_b[0]);
}

// ---------------- kernel: fused per-cluster sum + final blend -----------------
__global__ void __launch_bounds__(128) k_sal(float* __restrict__ out) {
    __shared__ float red[128];
    int k = blockIdx.x;
    int len = g_len[k], off = g_off[k];
    float s = 0.f;
    for (int t = threadIdx.x; t < len; t += 128) s += g_scores[g_sorted[off + t]];
    red[threadIdx.x] = s;
    __syncthreads();
    #pragma unroll
    for (int d = 64; d >= 1; d >>= 1) {
        if (threadIdx.x < d) red[threadIdx.x] += red[threadIdx.x + d];
        __syncthreads();
    }
    float inv_sum = 1.0f / red[0];
    const float INV = 0.0625f;  // 1 / 4096^(1/3)
    for (int t = threadIdx.x; t < len; t += 128) {
        int i = g_sorted[off + t];
        float sal = g_scores[i] * inv_sum;
        float pos = fmaxf(0.5f, expf(-((float)(i + 1)) * INV));
        out[i] = 0.5f * sal + 0.5f * pos;
    }
}

// ---------------- launch ----------------
extern "C" void kernel_launch(void* const* d_in, const int* in_sizes, int n_in,
                              void* d_out, int out_size) {
    const float* x      = (const float*)d_in[0];
    const int*   labels = (const int*)d_in[1];
    const float* W_ih0  = (const float*)d_in[2];
    const float* W_hh0  = (const float*)d_in[3];
    const float* b_ih0  = (const float*)d_in[4];
    const float* b_hh0  = (const float*)d_in[5];
    const float* W_ih1  = (const float*)d_in[6];
    const float* W_hh1  = (const float*)d_in[7];
    const float* b_ih1  = (const float*)d_in[8];
    const float* b_hh1  = (const float*)d_in[9];
    const float* lin_v  = (const float*)d_in[10];
    const float* lin_g  = (const float*)d_in[11];
    const float* lin_b  = (const float*)d_in[12];
    float* out = (float*)d_out;

    k_setup<<<1, 256>>>(labels);
    k_pack<<<96, 384>>>(W_ih0, W_ih1, b_ih0);
    k_xw0<<<NN / 16, 384>>>(x, b_ih0);
    k_gru<<<KK, 768>>>(W_hh0, b_hh0, 0);
    k_xw1<<<NR / 16, 384>>>(b_ih1);
    k_gru<<<KK, 768>>>(W_hh1, b_hh1, 1);
    k_score<<<NN / 128, 128>>>(x, labels, lin_v, lin_g, lin_b);
    k_sal<<<KK, 128>>>(out);
}

// round 8
// speedup vs baseline: 1.7992x; 1.7992x over previous
#include <cuda_runtime.h>
#include <cuda_bf16.h>

// Problem constants (fixed by the reference)
#define NN 4096
#define KK 32
#define DD 256
#define HH 128
#define GG 384   // 3*H
#define NR (NN + KK)   // h1 rows incl. one pad row per (possibly empty) cluster

typedef unsigned long long ull;

// ---------------- device scratch (no allocations allowed) ----------------
static __device__ float4 g_wih0p[64 * GG];   // W_ih0 packed [k4][g]
static __device__ float4 g_wih1p[32 * GG];   // W_ih1 packed [k4][g]
static __device__ float  g_xw0[NN * GG];     // x @ W_ih0^T + b_ih0
static __device__ float  g_xwz[GG];          // b_ih0 (zero-input row for empty clusters)
static __device__ float  g_h1[NR * HH];      // layer-0 hidden sequence
static __device__ float  g_xw1[NR * GG];     // h1 @ W_ih1^T + b_ih1
static __device__ int    g_sorted[NN];
static __device__ int    g_off[KK + 1];
static __device__ int    g_len[KK];
static __device__ float  g_emb[KK * HH];
static __device__ float  g_scores[NN];

// ---------------- helpers ----------------
static __device__ __forceinline__ ull ffma2(ull a, ull b, ull c) {
    ull d;
    asm("fma.rn.f32x2 %0, %1, %2, %3;" : "=l"(d) : "l"(a), "l"(b), "l"(c));
    return d;
}
static __device__ __forceinline__ float f2sum(ull v) {
    float a, b;
    asm("mov.b64 {%0, %1}, %2;" : "=f"(a), "=f"(b) : "l"(v));
    return a + b;
}
static __device__ __forceinline__ float ex2_(float x) {
    float y; asm("ex2.approx.f32 %0, %1;" : "=f"(y) : "f"(x)); return y;
}
static __device__ __forceinline__ float rcp_(float x) {
    float y; asm("rcp.approx.f32 %0, %1;" : "=f"(y) : "f"(x)); return y;
}
#define L2E 1.4426950408889634f
static __device__ __forceinline__ float fast_sigmoid(float x) {
    return rcp_(1.0f + ex2_(-x * L2E));
}
static __device__ __forceinline__ float fast_tanh(float x) {
    x = fminf(x, 20.0f);
    float e = ex2_(x * (2.0f * L2E));
    return (e - 1.0f) * rcp_(e + 1.0f);
}
static __device__ __forceinline__ void bar_sync_n(int id, int cnt) {
    asm volatile("bar.sync %0, %1;" :: "r"(id), "r"(cnt) : "memory");
}
static __device__ __forceinline__ void bar_arrive_n(int id, int cnt) {
    asm volatile("bar.arrive %0, %1;" :: "r"(id), "r"(cnt) : "memory");
}

// ---------------- kernel: cluster ordering (stable, parallel) ----------------
__global__ void k_setup(const int* __restrict__ labels) {
    __shared__ int ls[NN];
    __shared__ int cnt[8][KK];
    __shared__ int soff[8][KK];
    int t = threadIdx.x;                 // 256 threads
    for (int i = t; i < NN; i += 256) ls[i] = labels[i];
    __syncthreads();
    int w = t >> 5, k = t & 31;
    {
        int c = 0;
        const int4* p = (const int4*)(ls + w * 512);
        for (int ii = 0; ii < 128; ++ii) {
            int4 v = p[ii];
            c += (v.x == k) + (v.y == k) + (v.z == k) + (v.w == k);
        }
        cnt[w][k] = c;
    }
    __syncthreads();
    if (w == 0) {
        int tot = 0;
        #pragma unroll
        for (int s = 0; s < 8; ++s) tot += cnt[s][k];
        g_len[k] = tot;
        int v = tot;
        #pragma unroll
        for (int d = 1; d < 32; d <<= 1) {
            int y = __shfl_up_sync(0xffffffffu, v, d);
            if (k >= d) v += y;
        }
        int off = v - tot;
        g_off[k] = off;
        if (k == 31) g_off[32] = off + tot;
        int run = off;
        #pragma unroll
        for (int s = 0; s < 8; ++s) { soff[s][k] = run; run += cnt[s][k]; }
    }
    __syncthreads();
    {
        int c = soff[w][k];
        const int4* p = (const int4*)(ls + w * 512);
        for (int ii = 0; ii < 128; ++ii) {
            int4 v = p[ii];
            int b = w * 512 + ii * 4;
            if (v.x == k) g_sorted[c++] = b;
            if (v.y == k) g_sorted[c++] = b + 1;
            if (v.z == k) g_sorted[c++] = b + 2;
            if (v.w == k) g_sorted[c++] = b + 3;
        }
    }
}

// ---------------- kernel: pack input weights + zero-input row ----------------
__global__ void k_pack(const float* __restrict__ wih0, const float* __restrict__ wih1,
                       const float* __restrict__ b_ih0) {
    int b = blockIdx.x;          // 0..95
    int g = threadIdx.x;         // 0..383
    if (b < 64) {
        const float* row = wih0 + (size_t)g * DD + b * 4;
        g_wih0p[b * GG + g] = make_float4(row[0], row[1], row[2], row[3]);
        if (b == 0) g_xwz[g] = b_ih0[g];
    } else {
        int k4 = b - 64;
        const float* row = wih1 + (size_t)g * HH + k4 * 4;
        g_wih1p[k4 * GG + g] = make_float4(row[0], row[1], row[2], row[3]);
    }
}

// ---------------- kernel: xw0 = x @ W_ih0^T + b_ih0 ----------------
__global__ void __launch_bounds__(384) k_xw0(const float* __restrict__ x,
                                             const float* __restrict__ b_ih0) {
    __shared__ __align__(16) float xs[16 * DD];   // 16 KB
    int r0 = blockIdx.x * 16;
    {
        const float4* xsrc = reinterpret_cast<const float4*>(x + (size_t)r0 * DD);
        float4* xd = reinterpret_cast<float4*>(xs);
        for (int i = threadIdx.x; i < 16 * DD / 4; i += 384) xd[i] = xsrc[i];
    }
    __syncthreads();
    int g = threadIdx.x;
    ull acc[16];
    #pragma unroll
    for (int s = 0; s < 16; ++s) acc[s] = 0ull;
    const ulonglong2* W = reinterpret_cast<const ulonglong2*>(g_wih0p) + g;
    #pragma unroll 8
    for (int k4 = 0; k4 < 64; ++k4) {
        ulonglong2 w = W[k4 * GG];
        #pragma unroll
        for (int s = 0; s < 16; ++s) {
            ulonglong2 xv = *reinterpret_cast<const ulonglong2*>(&xs[s * DD + k4 * 4]);
            acc[s] = ffma2(w.x, xv.x, acc[s]);
            acc[s] = ffma2(w.y, xv.y, acc[s]);
        }
    }
    float bi = b_ih0[g];
    #pragma unroll
    for (int s = 0; s < 16; ++s)
        g_xw0[(size_t)(r0 + s) * GG + g] = f2sum(acc[s]) + bi;
}

// ---------------- kernel: xw1 = h1 @ W_ih1^T + b_ih1 (NR rows) ----------------
__global__ void __launch_bounds__(384) k_xw1(const float* __restrict__ b_ih1) {
    __shared__ __align__(16) float xs[16 * HH];   // 8 KB
    int r0 = blockIdx.x * 16;
    {
        const float4* xsrc = reinterpret_cast<const float4*>(g_h1 + (size_t)r0 * HH);
        float4* xd = reinterpret_cast<float4*>(xs);
        for (int i = threadIdx.x; i < 16 * HH / 4; i += 384) xd[i] = xsrc[i];
    }
    __syncthreads();
    int g = threadIdx.x;
    ull acc[16];
    #pragma unroll
    for (int s = 0; s < 16; ++s) acc[s] = 0ull;
    const ulonglong2* W = reinterpret_cast<const ulonglong2*>(g_wih1p) + g;
    #pragma unroll 8
    for (int k4 = 0; k4 < 32; ++k4) {
        ulonglong2 w = W[k4 * GG];
        #pragma unroll
        for (int s = 0; s < 16; ++s) {
            ulonglong2 xv = *reinterpret_cast<const ulonglong2*>(&xs[s * HH + k4 * 4]);
            acc[s] = ffma2(w.x, xv.x, acc[s]);
            acc[s] = ffma2(w.y, xv.y, acc[s]);
        }
    }
    float bi = b_ih1[g];
    #pragma unroll
    for (int s = 0; s < 16; ++s)
        g_xw1[(size_t)(r0 + s) * GG + g] = f2sum(acc[s]) + bi;
}

// ---------------- kernel: single-layer GRU recurrence, ONE CTA per cluster ----
// Thread t owns gate row t of W (384x128) in registers. Per step:
//   matvec (4 ILP chains) -> rows>=128 STS hw + bar.arrive(1); rows<128 keep
//   hw in reg, precompute r-gate BEFORE bar.sync(1) (overlaps barrier wait)
//   -> gates (z,n MUFU chains overlap; r ready) -> h write -> __syncthreads.
// No cross-SM traffic. pass 0: inputs g_xw0[g_sorted[...]], h1 seq -> g_h1.
// pass 1: inputs g_xw1 (sequential), final h -> g_emb.
__global__ void __launch_bounds__(384, 1) k_gru(const float* __restrict__ W,
                                                const float* __restrict__ bh,
                                                int pass) {
    __shared__ __align__(16) float h[HH];
    __shared__ float hw[GG];
    __shared__ __align__(16) float stage[64 * 132];   // 33.8 KB weight staging

    const int t = threadIdx.x;
    const int c = blockIdx.x;

    // ---- load weight row t into registers, smem-staged for coalescing
    ulonglong2 w[32];
    for (int grp = 0; grp < 6; ++grp) {
        const float4* src = reinterpret_cast<const float4*>(W + (size_t)(64 * grp) * HH);
        #pragma unroll
        for (int u = 0; u < 6; ++u) {
            int f = t + u * 384;              // float4 index within 64x128 block
            if (f < 2048) {
                int r = f >> 5, c4 = f & 31;
                *(float4*)&stage[r * 132 + c4 * 4] = src[f];
            }
        }
        __syncthreads();
        if ((t >> 6) == grp) {
            int r = t & 63;
            #pragma unroll
            for (int i = 0; i < 32; ++i)
                w[i] = *(const ulonglong2*)&stage[r * 132 + i * 4];
        }
        __syncthreads();
    }
    float bias = bh[t];
    if (t < HH) h[t] = 0.f;

    const int len = g_len[c], off = g_off[c];
    const int len_e = max(len, 1);

    // ---- input prefetch (threads 0..127 hold the 3 gate inputs for slot t)
    float xr = 0.f, xz = 0.f, xn = 0.f;
    int nidx = 0;
    if (t < HH) {
        const float* r0;
        if (pass == 0) r0 = (len > 0) ? (g_xw0 + (size_t)g_sorted[off] * GG) : g_xwz;
        else           r0 = g_xw1 + (size_t)((len > 0) ? off : (NN + c)) * GG;
        xr = r0[t]; xz = r0[HH + t]; xn = r0[2 * HH + t];
        if (pass == 0 && len > 1) nidx = g_sorted[off + 1];
    }
    __syncthreads();

    for (int it = 0; it < len_e; ++it) {
        // ---- matvec: row t dot h, 4 independent accumulation chains
        ull a0 = 0ull, a1 = 0ull, a2 = 0ull, a3 = 0ull;
        const ulonglong2* hp = reinterpret_cast<const ulonglong2*>(h);
        #pragma unroll
        for (int i = 0; i < 32; i += 2) {
            ulonglong2 hv0 = hp[i];
            ulonglong2 hv1 = hp[i + 1];
            a0 = ffma2(w[i].x,     hv0.x, a0);
            a1 = ffma2(w[i].y,     hv0.y, a1);
            a2 = ffma2(w[i + 1].x, hv1.x, a2);
            a3 = ffma2(w[i + 1].y, hv1.y, a3);
        }
        float myhw = (f2sum(a0) + f2sum(a1)) + (f2sum(a2) + f2sum(a3)) + bias;

        float r_pre = 0.f, hold = 0.f;
        if (t < HH) {
            // r-gate row is THIS thread's row: no STS/LDS, precompute r now
            // (overlaps the barrier wait below)
            r_pre = fast_sigmoid(xr + myhw);
            hold = h[t];
            bar_sync_n(1, 384);          // wait for z/n rows
        } else {
            hw[t] = myhw;                // z-rows (128..255), n-rows (256..383)
            bar_arrive_n(1, 384);        // non-blocking producer arrive
        }

        if (t < HH) {
            // prefetch next step's input row first (latency hidden by gates)
            float nxr = 0.f, nxz = 0.f, nxn = 0.f;
            bool more = (it + 1 < len_e);
            if (more) {
                const float* rn;
                if (pass == 0) rn = g_xw0 + (size_t)nidx * GG;
                else           rn = g_xw1 + (size_t)(off + it + 1) * GG;
                nxr = rn[t]; nxz = rn[HH + t]; nxn = rn[2 * HH + t];
                if (pass == 0 && it + 2 < len) nidx = g_sorted[off + it + 2];
            }
            // gates: r already computed; z and n MUFU chains overlap
            float z  = fast_sigmoid(xz + hw[HH + t]);
            float n  = fast_tanh(xn + r_pre * hw[2 * HH + t]);
            float hn = n + z * (hold - n);   // == (1-z)*n + z*h
            h[t] = hn;
            if (pass == 0) {
                int orow = (len > 0) ? (off + it) : (NN + c);
                g_h1[(size_t)orow * HH + t] = hn;
            }
            if (more) { xr = nxr; xz = nxz; xn = nxn; }
        }
        __syncthreads();   // h ready for next matvec
    }

    if (pass == 1 && t < HH) g_emb[c * HH + t] = h[t];
}

// ---------------- kernel: per-sentence tanh scores (weight-norm fused) -------
__global__ void __launch_bounds__(128) k_score(const float* __restrict__ x,
                                               const int* __restrict__ labels,
                                               const float* __restrict__ lin_v,
                                               const float* __restrict__ lin_g,
                                               const float* __restrict__ lin_b) {
    __shared__ __align__(16) float wns[GG];
    __shared__ __align__(16) float embs[KK][132];  // padded
    __shared__ float redw[4];
    int t = threadIdx.x;
    float v0 = lin_v[t], v1 = lin_v[HH + t], v2 = lin_v[2 * HH + t];
    float ss = v0 * v0 + v1 * v1 + v2 * v2;
    #pragma unroll
    for (int d = 16; d >= 1; d >>= 1) ss += __shfl_xor_sync(0xffffffffu, ss, d);
    if ((t & 31) == 0) redw[t >> 5] = ss;
    __syncthreads();
    float scale = lin_g[0] / sqrtf(redw[0] + redw[1] + redw[2] + redw[3]);
    wns[t] = v0 * scale; wns[HH + t] = v1 * scale; wns[2 * HH + t] = v2 * scale;
    for (int i = t; i < KK * HH; i += 128) embs[i >> 7][i & 127] = g_emb[i];
    __syncthreads();
    int i = blockIdx.x * 128 + t;
    int lab = labels[i];
    const float4* xr = reinterpret_cast<const float4*>(x) + (size_t)i * (DD / 4);
    float acc = 0.f;
    #pragma unroll 8
    for (int k4 = 0; k4 < DD / 4; ++k4) {
        float4 xv = xr[k4];
        float4 wv = *reinterpret_cast<const float4*>(&wns[k4 * 4]);
        acc = fmaf(xv.x, wv.x, acc); acc = fmaf(xv.y, wv.y, acc);
        acc = fmaf(xv.z, wv.z, acc); acc = fmaf(xv.w, wv.w, acc);
    }
    #pragma unroll 8
    for (int k4 = 0; k4 < HH / 4; ++k4) {
        float4 ev = *reinterpret_cast<const float4*>(&embs[lab][k4 * 4]);
        float4 wv = *reinterpret_cast<const float4*>(&wns[DD + k4 * 4]);
        acc = fmaf(ev.x, wv.x, acc); acc = fmaf(ev.y, wv.y, acc);
        acc = fmaf(ev.z, wv.z, acc); acc = fmaf(ev.w, wv.w, acc);
    }
    g_scores[i] = tanhf(acc + lin_b[0]);
}

// ---------------- kernel: fused per-cluster sum + final blend -----------------
__global__ void __launch_bounds__(128) k_sal(float* __restrict__ out) {
    __shared__ float red[128];
    int k = blockIdx.x;
    int len = g_len[k], off = g_off[k];
    float s = 0.f;
    for (int t = threadIdx.x; t < len; t += 128) s += g_scores[g_sorted[off + t]];
    red[threadIdx.x] = s;
    __syncthreads();
    #pragma unroll
    for (int d = 64; d >= 1; d >>= 1) {
        if (threadIdx.x < d) red[threadIdx.x] += red[threadIdx.x + d];
        __syncthreads();
    }
    float inv_sum = 1.0f / red[0];
    const float INV = 0.0625f;  // 1 / 4096^(1/3)
    for (int t = threadIdx.x; t < len; t += 128) {
        int i = g_sorted[off + t];
        float sal = g_scores[i] * inv_sum;
        float pos = fmaxf(0.5f, expf(-((float)(i + 1)) * INV));
        out[i] = 0.5f * sal + 0.5f * pos;
    }
}

// ---------------- launch ----------------
extern "C" void kernel_launch(void* const* d_in, const int* in_sizes, int n_in,
                              void* d_out, int out_size) {
    const float* x      = (const float*)d_in[0];
    const int*   labels = (const int*)d_in[1];
    const float* W_ih0  = (const float*)d_in[2];
    const float* W_hh0  = (const float*)d_in[3];
    const float* b_ih0  = (const float*)d_in[4];
    const float* b_hh0  = (const float*)d_in[5];
    const float* W_ih1  = (const float*)d_in[6];
    const float* W_hh1  = (const float*)d_in[7];
    const float* b_ih1  = (const float*)d_in[8];
    const float* b_hh1  = (const float*)d_in[9];
    const float* lin_v  = (const float*)d_in[10];
    const float* lin_g  = (const float*)d_in[11];
    const float* lin_b  = (const float*)d_in[12];
    float* out = (float*)d_out;

    k_setup<<<1, 256>>>(labels);
    k_pack<<<96, 384>>>(W_ih0, W_ih1, b_ih0);
    k_xw0<<<NN / 16, 384>>>(x, b_ih0);
    k_gru<<<KK, 384>>>(W_hh0, b_hh0, 0);
    k_xw1<<<NR / 16, 384>>>(b_ih1);
    k_gru<<<KK, 384>>>(W_hh1, b_hh1, 1);
    k_score<<<NN / 128, 128>>>(x, labels, lin_v, lin_g, lin_b);
    k_sal<<<KK, 128>>>(out);
}